// round 16
// baseline (speedup 1.0000x reference)
#include <cuda_runtime.h>
#include <cuda_fp16.h>
#include <math.h>
#include <stdint.h>

#define NNODES 50000
#define NEDGES 1600000
#define INDIM  6
#define HID    128
#define NEXP   4
#define NLAY   3
#define NGRAPH 16
#define INV_LOGN 0.10857362047581294f  /* 1/log(1e4) */

#define ESTR   (NNODES*HID)            /* per-expert elem stride: 6.4M */
#define NB1K   ((NNODES+1023)/1024)    /* 49 scan blocks */
#define GTILES ((NNODES+127)/128)      /* 391 M-tiles */
#define APAD   72                      /* fp16 row stride in smem */
#define AGG_SCALE  0.015625f           /* 2^-6: keeps fp16 agg in range */
#define WN_SCALE   64.0f               /* compensation on W_nbr */

#define NZB    ((NNODES+255)/256)
#define HEB    ((NEDGES+255)/256)      /* 6250 edge-hist blocks */
#define ENCB   ((NNODES+63)/64)        /* 782 encoder blocks */
#define PRBB   ((NNODES+255)/256)

/* ------------------------------ scratch ------------------------------ */
__device__ int   g_is64;
__device__ int   g_deg[NNODES];
__device__ int   g_rowptr[NNODES+1];
__device__ int   g_fill[NNODES];
__device__ int   g_srcsorted[NEDGES];
__device__ int   g_part[64];
__device__ int   g_gcount[NGRAPH];
__device__ __align__(16) float  g_hA[NEXP*ESTR];     /* fp32, final layer out */
__device__ __align__(16) float  g_probs[NNODES*NEXP];
__device__ __align__(16) __half g_h16a[NEXP*ESTR];   /* fp16 state ping */
__device__ __align__(16) __half g_h16b[NEXP*ESTR];   /* fp16 state pong */
__device__ __align__(16) __half g_agg16[NEXP*ESTR];  /* fp16 scaled aggregation */
__device__ __align__(16) __half g_wf[NEXP*NLAY*HID*256];

__device__ __forceinline__ __half* buf16(int sel) { return sel ? g_h16b : g_h16a; }

__device__ __forceinline__ int idx_at(const void* p, long long i, int is64) {
    if (is64) return (int)((const long long*)p)[i];
    return ((const int*)p)[i];
}

__device__ __forceinline__ void mma_f16(float* c, uint32_t a0, uint32_t a1,
                                        uint32_t a2, uint32_t a3,
                                        uint32_t b0, uint32_t b1) {
    asm volatile(
        "mma.sync.aligned.m16n8k16.row.col.f32.f16.f16.f32 "
        "{%0,%1,%2,%3}, {%4,%5,%6,%7}, {%8,%9}, {%0,%1,%2,%3};"
        : "+f"(c[0]), "+f"(c[1]), "+f"(c[2]), "+f"(c[3])
        : "r"(a0), "r"(a1), "r"(a2), "r"(a3), "r"(b0), "r"(b1));
}

/* ------------------------------ zero + dtype probe ------------------------------ */
__global__ void k_zero_detect(const unsigned int* w) {
    int i = blockIdx.x*blockDim.x + threadIdx.x;
    if (i < NNODES) g_deg[i] = 0;
    if (i < NGRAPH) g_gcount[i] = 0;
    if (blockIdx.x == 0) {
        unsigned v = (threadIdx.x < 128) ? __ldg(&w[2*threadIdx.x + 1]) : 0u;
        int any = __syncthreads_or(v != 0u);
        if (threadIdx.x == 0) g_is64 = !any;
    }
}

/* ------------------------------ histograms (edges + batch) ------------------------------ */
__global__ void k_hist(const void* __restrict__ ei, const void* __restrict__ batch) {
    int is64 = g_is64;
    if (blockIdx.x < HEB) {
        int i = blockIdx.x*blockDim.x + threadIdx.x;
        if (i < NEDGES) {
            int dst = idx_at(ei, (long long)NEDGES + i, is64);
            atomicAdd(&g_deg[dst], 1);
        }
    } else {
        __shared__ int sh[NGRAPH];
        if (threadIdx.x < NGRAPH) sh[threadIdx.x] = 0;
        __syncthreads();
        for (int i = (blockIdx.x - HEB)*blockDim.x + threadIdx.x; i < NNODES; i += 64*blockDim.x)
            atomicAdd(&sh[idx_at(batch, i, is64)], 1);
        __syncthreads();
        if (threadIdx.x < NGRAPH) atomicAdd(&g_gcount[threadIdx.x], sh[threadIdx.x]);
    }
}

__global__ void k_scan1() {
    __shared__ int s[1024];
    int t = threadIdx.x;
    int idx = blockIdx.x*1024 + t;
    int v = (idx < NNODES) ? g_deg[idx] : 0;
    s[t] = v;
    __syncthreads();
    for (int off = 1; off < 1024; off <<= 1) {
        int a = (t >= off) ? s[t-off] : 0;
        __syncthreads();
        s[t] += a;
        __syncthreads();
    }
    if (idx < NNODES) g_rowptr[idx] = s[t] - v;
    if (t == 1023)   g_part[blockIdx.x] = s[1023];
}

__global__ void k_scan2() {
    __shared__ int s[64];
    int t = threadIdx.x;
    int v = (t < NB1K) ? g_part[t] : 0;
    s[t] = v;
    __syncthreads();
    for (int off = 1; off < 64; off <<= 1) {
        int a = (t >= off) ? s[t-off] : 0;
        __syncthreads();
        s[t] += a;
        __syncthreads();
    }
    if (t < NB1K) g_part[t] = s[t] - v;
}

__global__ void k_scan3() {
    int idx = blockIdx.x*1024 + threadIdx.x;
    if (idx < NNODES) {
        int r = g_rowptr[idx] + g_part[blockIdx.x];
        g_rowptr[idx] = r;
        g_fill[idx]   = r;
    }
    if (idx == 0) g_rowptr[NNODES] = NEDGES;
}

__global__ void k_scatter(const void* __restrict__ ei) {
    int is64 = g_is64;
    int i = blockIdx.x*blockDim.x + threadIdx.x;
    if (i < NEDGES) {
        int src = idx_at(ei, i, is64);
        int dst = idx_at(ei, (long long)NEDGES + i, is64);
        int pos = atomicAdd(&g_fill[dst], 1);
        g_srcsorted[pos] = src;
    }
}

/* ------------------------------ weight prep + encoder (side stream) ------------------------------ */
__global__ void k_wsplit_enc(const float* __restrict__ Ws, const float* __restrict__ Wn,
                             const float* __restrict__ x,
                             const float* __restrict__ W, const float* __restrict__ b) {
    if (blockIdx.x < NEXP*NLAY) {
        int el = blockIdx.x;
        int e = el / NLAY, l = el % NLAY;
        const float* S  = Ws + ((size_t)e*NLAY + l)*HID*HID;
        const float* Nw = Wn + ((size_t)e*NLAY + l)*HID*HID;
        __half* oh = g_wf + (size_t)el*HID*256;
        for (int idx = threadIdx.x; idx < HID*256; idx += blockDim.x) {
            int n = idx >> 8;
            int k = idx & 255;
            float v = (k < HID) ? S[(size_t)k*HID + n]
                                : Nw[(size_t)(k-HID)*HID + n] * WN_SCALE;
            oh[idx] = __float2half_rn(v);
        }
    } else {
        __shared__ float sW[INDIM*HID];
        __shared__ float sb[HID];
        __shared__ float sx[64*INDIM];
        int t = threadIdx.x;
        int n0 = (blockIdx.x - NEXP*NLAY)*64;
        for (int i = t; i < INDIM*HID; i += 256) sW[i] = W[i];
        if (t < HID) sb[t] = b[t];
        for (int i = t; i < 64*INDIM; i += 256) {
            int gi = n0*INDIM + i;
            sx[i] = (gi < NNODES*INDIM) ? x[gi] : 0.f;
        }
        __syncthreads();
        int col = t & 127, half = t >> 7;
        for (int nn = 0; nn < 32; nn++) {
            int n = n0 + half*32 + nn;
            if (n >= NNODES) break;
            float acc = sb[col];
            #pragma unroll
            for (int k = 0; k < INDIM; k++) acc += sx[(half*32 + nn)*INDIM + k] * sW[k*HID + col];
            g_h16a[(size_t)n*HID + col] = __float2half_rn(fmaxf(acc, 0.f));
        }
    }
}

/* ------------------------------ prior ------------------------------ */
__global__ void k_probs(const void* __restrict__ batch,
                        const float* __restrict__ centers) {
    int is64 = g_is64;
    int n = blockIdx.x*blockDim.x + threadIdx.x;
    if (n >= NNODES) return;
    float c = (float)g_gcount[idx_at(batch, n, is64)];
    float logn = logf(fmaxf(c, 1.0f)) * INV_LOGN;
    float v[NEXP], m = -1e30f;
    #pragma unroll
    for (int e = 0; e < NEXP; e++) {
        float d = logn - centers[e];
        v[e] = -d*d;
        m = fmaxf(m, v[e]);
    }
    float sum = 0.f;
    #pragma unroll
    for (int e = 0; e < NEXP; e++) { v[e] = expf(v[e] - m); sum += v[e]; }
    float inv = 1.0f / sum;
    #pragma unroll
    for (int e = 0; e < NEXP; e++) g_probs[n*NEXP + e] = v[e]*inv;
}

/* ------------------------------ SpMM (paired-edge uint4 gather) ------------------------------ */
/* half-warp per edge: 16 lanes x uint4(16B) = 256B row; warp does 2 edges/iter */
template<int NE>
__global__ void k_spmm16(int hin_sel) {
    int gw   = (blockIdx.x*blockDim.x + threadIdx.x) >> 5;
    int lane = threadIdx.x & 31;
    if (gw >= NNODES) return;
    int start = g_rowptr[gw], end = g_rowptr[gw+1];
    int half = lane >> 4;                 /* 0: edge j, 1: edge j+1 */
    int hl   = lane & 15;
    float acc[NE][8];
    #pragma unroll
    for (int e = 0; e < NE; e++)
        #pragma unroll
        for (int q = 0; q < 8; q++) acc[e][q] = 0.f;
    const uint4* h4 = (const uint4*)buf16(hin_sel);   /* row = 16 uint4 */
    for (int base = start; base < end; base += 32) {
        int rem = end - base;
        int cnt = rem < 32 ? rem : 32;
        int idx = (lane < cnt) ? g_srcsorted[base + lane] : 0;
        for (int j = 0; j < cnt; j += 2) {
            int jj = j + half;
            int valid = (jj < cnt);
            int s = __shfl_sync(0xffffffffu, idx, valid ? jj : j);
            uint4 v[NE];
            #pragma unroll
            for (int e = 0; e < NE; e++)
                v[e] = __ldg(&h4[(size_t)s*16 + hl + (size_t)e*(NNODES*16)]);
            if (valid) {
                #pragma unroll
                for (int e = 0; e < NE; e++) {
                    const __half2* hv = (const __half2*)&v[e];
                    #pragma unroll
                    for (int q = 0; q < 4; q++) {
                        float2 f = __half22float2(hv[q]);
                        acc[e][q*2]   += f.x;
                        acc[e][q*2+1] += f.y;
                    }
                }
            }
        }
    }
    /* merge high half into low half */
    #pragma unroll
    for (int e = 0; e < NE; e++)
        #pragma unroll
        for (int q = 0; q < 8; q++)
            acc[e][q] += __shfl_down_sync(0xffffffffu, acc[e][q], 16);
    if (half == 0) {
        size_t oo = (size_t)gw*16 + hl;
        #pragma unroll
        for (int e = 0; e < NE; e++) {
            uint4 o;
            __half2* ho = (__half2*)&o;
            #pragma unroll
            for (int q = 0; q < 4; q++)
                ho[q] = __floats2half2_rn(acc[e][q*2]*AGG_SCALE, acc[e][q*2+1]*AGG_SCALE);
            ((uint4*)g_agg16)[oo + (size_t)e*(NNODES*16)] = o;
        }
    }
}

/* ------------------------------ fp16 GEMM (A fp16, single fp16 weight) ------------------------------ */
#define SM_A  0
#define SM_B  (128*APAD)
#define SMEM_TOT (2*128*APAD*2)

template<bool RELU, bool W16, bool S32>
__global__ void __launch_bounds__(256)
k_gemm_mma(int hin_sel, size_t hin_es, int hout_sel, int lidx,
           const float* __restrict__ b_conv)
{
    extern __shared__ __align__(16) __half sm[];
    int t = threadIdx.x, lane = t & 31, wid = t >> 5;
    int wr = (wid & 1)*64, wc = (wid >> 1)*32;
    int e = blockIdx.y;
    int row0 = blockIdx.x * 128;

    const __half* A1 = buf16(hin_sel) + (size_t)e*hin_es;
    const __half* A2 = g_agg16        + (size_t)e*hin_es;
    int el = e*NLAY + lidx;
    const __half* WB = g_wf + (size_t)el*HID*256;
    const float* bi = b_conv + (size_t)el*HID;
    float*  ho   = g_hA + (size_t)e*ESTR;
    __half* ho16 = buf16(hout_sel) + (size_t)e*ESTR;

    float acc[16][4];
    #pragma unroll
    for (int i = 0; i < 16; i++)
        #pragma unroll
        for (int j = 0; j < 4; j++) acc[i][j] = 0.f;

    int lr = t >> 1;
    int gr = row0 + lr; if (gr >= NNODES) gr = NNODES - 1;

    #pragma unroll 1
    for (int c = 0; c < 4; c++) {
        __syncthreads();
        const __half* Ab = ((c < 2) ? A1 : A2) + (size_t)gr*HID + (c & 1)*64;
        const __half* Bb = WB + (size_t)lr*256 + c*64;
        #pragma unroll
        for (int j = 0; j < 4; j++) {
            int q = (t & 1)*4 + j;
            *(uint4*)&sm[SM_A + lr*APAD + q*8] = *(const uint4*)(Ab + q*8);
            *(uint4*)&sm[SM_B + lr*APAD + q*8] = *(const uint4*)(Bb + q*8);
        }
        __syncthreads();

        #pragma unroll
        for (int ks = 0; ks < 4; ks++) {
            int kk = ks*16 + (lane & 3)*2;
            uint32_t b_[4][2];
            #pragma unroll
            for (int nt = 0; nt < 4; nt++) {
                int col = wc + nt*8 + (lane >> 2);
                b_[nt][0] = *(const uint32_t*)&sm[SM_B + col*APAD + kk];
                b_[nt][1] = *(const uint32_t*)&sm[SM_B + col*APAD + kk + 8];
            }
            #pragma unroll
            for (int mt = 0; mt < 4; mt++) {
                int ra = wr + mt*16 + (lane >> 2);
                uint32_t a0 = *(const uint32_t*)&sm[SM_A + ra*APAD + kk];
                uint32_t a1 = *(const uint32_t*)&sm[SM_A + (ra+8)*APAD + kk];
                uint32_t a2 = *(const uint32_t*)&sm[SM_A + ra*APAD + kk + 8];
                uint32_t a3 = *(const uint32_t*)&sm[SM_A + (ra+8)*APAD + kk + 8];
                #pragma unroll
                for (int nt = 0; nt < 4; nt++)
                    mma_f16(acc[mt*4 + nt], a0, a1, a2, a3, b_[nt][0], b_[nt][1]);
            }
        }
    }

    #pragma unroll
    for (int nt = 0; nt < 4; nt++) {
        int col = wc + nt*8 + (lane & 3)*2;
        float2 bv = *(const float2*)&bi[col];
        #pragma unroll
        for (int mt = 0; mt < 4; mt++) {
            const float* cc = acc[mt*4 + nt];
            int r0 = row0 + wr + mt*16 + (lane >> 2);
            float2 v0, v1;
            v0.x = cc[0] + bv.x; v0.y = cc[1] + bv.y;
            v1.x = cc[2] + bv.x; v1.y = cc[3] + bv.y;
            if (RELU) {
                v0.x = fmaxf(v0.x, 0.f); v0.y = fmaxf(v0.y, 0.f);
                v1.x = fmaxf(v1.x, 0.f); v1.y = fmaxf(v1.y, 0.f);
            }
            if (r0 < NNODES) {
                if (S32) *(float2*)&ho[(size_t)r0*HID + col] = v0;
                if (W16) *(__half2*)&ho16[(size_t)r0*HID + col] = __floats2half2_rn(v0.x, v0.y);
            }
            if (r0 + 8 < NNODES) {
                if (S32) *(float2*)&ho[(size_t)(r0+8)*HID + col] = v1;
                if (W16) *(__half2*)&ho16[(size_t)(r0+8)*HID + col] = __floats2half2_rn(v1.x, v1.y);
            }
        }
    }
}

/* ------------------------------ combine ------------------------------ */
__global__ void k_combine(float* __restrict__ out) {
    int i = blockIdx.x*blockDim.x + threadIdx.x;
    if (i >= NNODES*32) return;
    int n = i >> 5;
    float4 p = *(const float4*)&g_probs[n*NEXP];
    const float4* h4 = (const float4*)g_hA;
    float4 v0 = h4[i];
    float4 v1 = h4[i + (size_t)1*(NNODES*32)];
    float4 v2 = h4[i + (size_t)2*(NNODES*32)];
    float4 v3 = h4[i + (size_t)3*(NNODES*32)];
    float4 r;
    r.x = p.x*v0.x + p.y*v1.x + p.z*v2.x + p.w*v3.x;
    r.y = p.x*v0.y + p.y*v1.y + p.z*v2.y + p.w*v3.y;
    r.z = p.x*v0.z + p.y*v1.z + p.z*v2.z + p.w*v3.z;
    r.w = p.x*v0.w + p.y*v1.w + p.z*v2.w + p.w*v3.w;
    ((float4*)out)[i] = r;
}

/* ------------------------------ launch (prep fork only; layers serialized) ------------------------------ */
extern "C" void kernel_launch(void* const* d_in, const int* in_sizes, int n_in,
                              void* d_out, int out_size) {
    const float* x       = (const float*)d_in[0];
    const void*  ei      = d_in[1];
    const void*  batch   = d_in[2];
    const float* W_enc   = (const float*)d_in[3];
    const float* b_enc   = (const float*)d_in[4];
    const float* W_self  = (const float*)d_in[5];
    const float* W_nbr   = (const float*)d_in[6];
    const float* b_conv  = (const float*)d_in[7];
    const float* centers = (const float*)d_in[8];
    float*       out     = (float*)d_out;

    static cudaStream_t s2 = nullptr;
    static cudaEvent_t  ev0, ev1;
    if (!s2) {
        cudaStreamCreateWithFlags(&s2, cudaStreamNonBlocking);
        cudaEventCreateWithFlags(&ev0, cudaEventDisableTiming);
        cudaEventCreateWithFlags(&ev1, cudaEventDisableTiming);
    }

    /* fork: weights + encoder on s2, concurrent with CSR chain on capture stream */
    k_zero_detect<<<NZB, 256>>>((const unsigned int*)ei);
    cudaEventRecord(ev0, 0);
    cudaStreamWaitEvent(s2, ev0, 0);
    k_wsplit_enc<<<NEXP*NLAY + ENCB, 256, 0, s2>>>(W_self, W_nbr, x, W_enc, b_enc);
    cudaEventRecord(ev1, s2);

    k_hist   <<<HEB + 64, 256>>>(ei, batch);
    k_probs  <<<PRBB, 256>>>(batch, centers);
    k_scan1  <<<NB1K, 1024>>>();
    k_scan2  <<<1, 64>>>();
    k_scan3  <<<NB1K, 1024>>>();
    k_scatter<<<HEB, 256>>>(ei);
    cudaStreamWaitEvent(0, ev1, 0);   /* join: encoder h16a + weights ready */

    dim3 gemm_grid(GTILES, NEXP);
    int  spmm_blocks = (NNODES*32 + 255)/256;

    /* layer 0: h0 in bufA slot 0 -> 1 gather; GEMM reads bufA, writes bufB */
    k_spmm16<1><<<spmm_blocks, 256>>>(0);
    k_gemm_mma<true,true,false><<<gemm_grid, 256, SMEM_TOT>>>(0, 0, 1, 0, b_conv);

    /* layer 1: gather bufB -> agg; GEMM bufB -> bufA */
    k_spmm16<4><<<spmm_blocks, 256>>>(1);
    k_gemm_mma<true,true,false><<<gemm_grid, 256, SMEM_TOT>>>(1, (size_t)ESTR, 0, 1, b_conv);

    /* layer 2: gather bufA -> agg; GEMM bufA -> fp32 hA (no relu) */
    k_spmm16<4><<<spmm_blocks, 256>>>(0);
    k_gemm_mma<false,false,true><<<gemm_grid, 256, SMEM_TOT>>>(0, (size_t)ESTR, 0, 2, b_conv);

    /* prior-weighted mix */
    k_combine<<<(NNODES*32 + 255)/256, 256>>>(out);
}

// round 17
// speedup vs baseline: 1.0598x; 1.0598x over previous
#include <cuda_runtime.h>
#include <cuda_fp16.h>
#include <math.h>
#include <stdint.h>

#define NNODES 50000
#define NEDGES 1600000
#define INDIM  6
#define HID    128
#define NEXP   4
#define NLAY   3
#define NGRAPH 16
#define INV_LOGN 0.10857362047581294f  /* 1/log(1e4) */

#define ESTR   (NNODES*HID)            /* per-expert elem stride: 6.4M */
#define NB1K   ((NNODES+1023)/1024)    /* 49 scan blocks */
#define GTILES ((NNODES+127)/128)      /* 391 M-tiles */
#define APAD   72                      /* fp16 row stride in smem */
#define AGG_SCALE  0.015625f           /* 2^-6: keeps fp16 agg in range */
#define WN_SCALE   64.0f               /* compensation on W_nbr */

#define NZB    ((NNODES+255)/256)
#define HEB    ((NEDGES+255)/256)      /* 6250 edge-hist blocks */
#define ENCB   ((NNODES+63)/64)        /* 782 encoder blocks */
#define PRBB   ((NNODES+255)/256)

/* ------------------------------ scratch ------------------------------ */
__device__ int   g_is64;
__device__ int   g_deg[NNODES];
__device__ int   g_rowptr[NNODES+1];
__device__ int   g_fill[NNODES];
__device__ int   g_srcsorted[NEDGES];
__device__ int   g_part[64];
__device__ int   g_gcount[NGRAPH];
__device__ __align__(16) float  g_hA[NEXP*ESTR];     /* fp32, final layer out */
__device__ __align__(16) float  g_probs[NNODES*NEXP];
__device__ __align__(16) __half g_h16a[NEXP*ESTR];   /* fp16 state ping */
__device__ __align__(16) __half g_h16b[NEXP*ESTR];   /* fp16 state pong */
__device__ __align__(16) __half g_agg16[NEXP*ESTR];  /* fp16 scaled aggregation */
__device__ __align__(16) __half g_wf[NEXP*NLAY*HID*256];

__device__ __forceinline__ __half* buf16(int sel) { return sel ? g_h16b : g_h16a; }

__device__ __forceinline__ int idx_at(const void* p, long long i, int is64) {
    if (is64) return (int)((const long long*)p)[i];
    return ((const int*)p)[i];
}

__device__ __forceinline__ void mma_f16(float* c, uint32_t a0, uint32_t a1,
                                        uint32_t a2, uint32_t a3,
                                        uint32_t b0, uint32_t b1) {
    asm volatile(
        "mma.sync.aligned.m16n8k16.row.col.f32.f16.f16.f32 "
        "{%0,%1,%2,%3}, {%4,%5,%6,%7}, {%8,%9}, {%0,%1,%2,%3};"
        : "+f"(c[0]), "+f"(c[1]), "+f"(c[2]), "+f"(c[3])
        : "r"(a0), "r"(a1), "r"(a2), "r"(a3), "r"(b0), "r"(b1));
}

/* ------------------------------ zero + dtype probe ------------------------------ */
__global__ void k_zero_detect(const unsigned int* w) {
    int i = blockIdx.x*blockDim.x + threadIdx.x;
    if (i < NNODES) g_deg[i] = 0;
    if (i < NGRAPH) g_gcount[i] = 0;
    if (blockIdx.x == 0) {
        unsigned v = (threadIdx.x < 128) ? __ldg(&w[2*threadIdx.x + 1]) : 0u;
        int any = __syncthreads_or(v != 0u);
        if (threadIdx.x == 0) g_is64 = !any;
    }
}

/* ------------------------------ histograms (edges + batch) ------------------------------ */
__global__ void k_hist(const void* __restrict__ ei, const void* __restrict__ batch) {
    int is64 = g_is64;
    if (blockIdx.x < HEB) {
        int i = blockIdx.x*blockDim.x + threadIdx.x;
        if (i < NEDGES) {
            int dst = idx_at(ei, (long long)NEDGES + i, is64);
            atomicAdd(&g_deg[dst], 1);
        }
    } else {
        __shared__ int sh[NGRAPH];
        if (threadIdx.x < NGRAPH) sh[threadIdx.x] = 0;
        __syncthreads();
        for (int i = (blockIdx.x - HEB)*blockDim.x + threadIdx.x; i < NNODES; i += 64*blockDim.x)
            atomicAdd(&sh[idx_at(batch, i, is64)], 1);
        __syncthreads();
        if (threadIdx.x < NGRAPH) atomicAdd(&g_gcount[threadIdx.x], sh[threadIdx.x]);
    }
}

__global__ void k_scan1() {
    __shared__ int s[1024];
    int t = threadIdx.x;
    int idx = blockIdx.x*1024 + t;
    int v = (idx < NNODES) ? g_deg[idx] : 0;
    s[t] = v;
    __syncthreads();
    for (int off = 1; off < 1024; off <<= 1) {
        int a = (t >= off) ? s[t-off] : 0;
        __syncthreads();
        s[t] += a;
        __syncthreads();
    }
    if (idx < NNODES) g_rowptr[idx] = s[t] - v;
    if (t == 1023)   g_part[blockIdx.x] = s[1023];
}

__global__ void k_scan2() {
    __shared__ int s[64];
    int t = threadIdx.x;
    int v = (t < NB1K) ? g_part[t] : 0;
    s[t] = v;
    __syncthreads();
    for (int off = 1; off < 64; off <<= 1) {
        int a = (t >= off) ? s[t-off] : 0;
        __syncthreads();
        s[t] += a;
        __syncthreads();
    }
    if (t < NB1K) g_part[t] = s[t] - v;
}

__global__ void k_scan3() {
    int idx = blockIdx.x*1024 + threadIdx.x;
    if (idx < NNODES) {
        int r = g_rowptr[idx] + g_part[blockIdx.x];
        g_rowptr[idx] = r;
        g_fill[idx]   = r;
    }
    if (idx == 0) g_rowptr[NNODES] = NEDGES;
}

__global__ void k_scatter(const void* __restrict__ ei) {
    int is64 = g_is64;
    int i = blockIdx.x*blockDim.x + threadIdx.x;
    if (i < NEDGES) {
        int src = idx_at(ei, i, is64);
        int dst = idx_at(ei, (long long)NEDGES + i, is64);
        int pos = atomicAdd(&g_fill[dst], 1);
        g_srcsorted[pos] = src;
    }
}

/* ------------------------------ weight prep + encoder (side stream) ------------------------------ */
__global__ void k_wsplit_enc(const float* __restrict__ Ws, const float* __restrict__ Wn,
                             const float* __restrict__ x,
                             const float* __restrict__ W, const float* __restrict__ b) {
    if (blockIdx.x < NEXP*NLAY) {
        int el = blockIdx.x;
        int e = el / NLAY, l = el % NLAY;
        const float* S  = Ws + ((size_t)e*NLAY + l)*HID*HID;
        const float* Nw = Wn + ((size_t)e*NLAY + l)*HID*HID;
        __half* oh = g_wf + (size_t)el*HID*256;
        for (int idx = threadIdx.x; idx < HID*256; idx += blockDim.x) {
            int n = idx >> 8;
            int k = idx & 255;
            float v = (k < HID) ? S[(size_t)k*HID + n]
                                : Nw[(size_t)(k-HID)*HID + n] * WN_SCALE;
            oh[idx] = __float2half_rn(v);
        }
    } else {
        __shared__ float sW[INDIM*HID];
        __shared__ float sb[HID];
        __shared__ float sx[64*INDIM];
        int t = threadIdx.x;
        int n0 = (blockIdx.x - NEXP*NLAY)*64;
        for (int i = t; i < INDIM*HID; i += 256) sW[i] = W[i];
        if (t < HID) sb[t] = b[t];
        for (int i = t; i < 64*INDIM; i += 256) {
            int gi = n0*INDIM + i;
            sx[i] = (gi < NNODES*INDIM) ? x[gi] : 0.f;
        }
        __syncthreads();
        int col = t & 127, half = t >> 7;
        for (int nn = 0; nn < 32; nn++) {
            int n = n0 + half*32 + nn;
            if (n >= NNODES) break;
            float acc = sb[col];
            #pragma unroll
            for (int k = 0; k < INDIM; k++) acc += sx[(half*32 + nn)*INDIM + k] * sW[k*HID + col];
            g_h16a[(size_t)n*HID + col] = __float2half_rn(fmaxf(acc, 0.f));
        }
    }
}

/* ------------------------------ prior (side stream, after hist) ------------------------------ */
__global__ void k_probs(const void* __restrict__ batch,
                        const float* __restrict__ centers) {
    int is64 = g_is64;
    int n = blockIdx.x*blockDim.x + threadIdx.x;
    if (n >= NNODES) return;
    float c = (float)g_gcount[idx_at(batch, n, is64)];
    float logn = logf(fmaxf(c, 1.0f)) * INV_LOGN;
    float v[NEXP], m = -1e30f;
    #pragma unroll
    for (int e = 0; e < NEXP; e++) {
        float d = logn - centers[e];
        v[e] = -d*d;
        m = fmaxf(m, v[e]);
    }
    float sum = 0.f;
    #pragma unroll
    for (int e = 0; e < NEXP; e++) { v[e] = expf(v[e] - m); sum += v[e]; }
    float inv = 1.0f / sum;
    #pragma unroll
    for (int e = 0; e < NEXP; e++) g_probs[n*NEXP + e] = v[e]*inv;
}

/* ------------------------------ SpMM (CSR, warp/node, shfl window, fp16) ------------------------------ */
template<int NE>
__global__ void k_spmm16(int hin_sel) {
    int gw   = (blockIdx.x*blockDim.x + threadIdx.x) >> 5;
    int lane = threadIdx.x & 31;
    if (gw >= NNODES) return;
    int start = g_rowptr[gw], end = g_rowptr[gw+1];
    float acc[NE][4];
    #pragma unroll
    for (int e = 0; e < NE; e++)
        #pragma unroll
        for (int j = 0; j < 4; j++) acc[e][j] = 0.f;
    const uint2* h2 = (const uint2*)buf16(hin_sel);
    for (int base = start; base < end; base += 32) {
        int rem = end - base;
        int cnt = rem < 32 ? rem : 32;
        int idx = (lane < cnt) ? g_srcsorted[base + lane] : 0;
        for (int j = 0; j < cnt; j++) {
            int s = __shfl_sync(0xffffffffu, idx, j);
            size_t o = (size_t)s*32 + lane;
            #pragma unroll
            for (int e = 0; e < NE; e++) {
                uint2 v = __ldg(&h2[o + (size_t)e*(NNODES*32)]);
                float2 a = __half22float2(*(const __half2*)&v.x);
                float2 b = __half22float2(*(const __half2*)&v.y);
                acc[e][0] += a.x; acc[e][1] += a.y; acc[e][2] += b.x; acc[e][3] += b.y;
            }
        }
    }
    size_t oo = (size_t)gw*32 + lane;
    #pragma unroll
    for (int e = 0; e < NE; e++) {
        uint2 o;
        *(__half2*)&o.x = __floats2half2_rn(acc[e][0]*AGG_SCALE, acc[e][1]*AGG_SCALE);
        *(__half2*)&o.y = __floats2half2_rn(acc[e][2]*AGG_SCALE, acc[e][3]*AGG_SCALE);
        ((uint2*)g_agg16)[oo + (size_t)e*(NNODES*32)] = o;
    }
}

/* ------------------------------ fp16 GEMM (A fp16, single fp16 weight) ------------------------------ */
#define SM_A  0
#define SM_B  (128*APAD)
#define SMEM_TOT (2*128*APAD*2)

template<bool RELU, bool W16, bool S32>
__global__ void __launch_bounds__(256)
k_gemm_mma(int hin_sel, size_t hin_es, int hout_sel, int lidx,
           const float* __restrict__ b_conv)
{
    extern __shared__ __align__(16) __half sm[];
    int t = threadIdx.x, lane = t & 31, wid = t >> 5;
    int wr = (wid & 1)*64, wc = (wid >> 1)*32;
    int e = blockIdx.y;
    int row0 = blockIdx.x * 128;

    const __half* A1 = buf16(hin_sel) + (size_t)e*hin_es;
    const __half* A2 = g_agg16        + (size_t)e*hin_es;
    int el = e*NLAY + lidx;
    const __half* WB = g_wf + (size_t)el*HID*256;
    const float* bi = b_conv + (size_t)el*HID;
    float*  ho   = g_hA + (size_t)e*ESTR;
    __half* ho16 = buf16(hout_sel) + (size_t)e*ESTR;

    float acc[16][4];
    #pragma unroll
    for (int i = 0; i < 16; i++)
        #pragma unroll
        for (int j = 0; j < 4; j++) acc[i][j] = 0.f;

    int lr = t >> 1;
    int gr = row0 + lr; if (gr >= NNODES) gr = NNODES - 1;

    #pragma unroll 1
    for (int c = 0; c < 4; c++) {
        __syncthreads();
        const __half* Ab = ((c < 2) ? A1 : A2) + (size_t)gr*HID + (c & 1)*64;
        const __half* Bb = WB + (size_t)lr*256 + c*64;
        #pragma unroll
        for (int j = 0; j < 4; j++) {
            int q = (t & 1)*4 + j;
            *(uint4*)&sm[SM_A + lr*APAD + q*8] = *(const uint4*)(Ab + q*8);
            *(uint4*)&sm[SM_B + lr*APAD + q*8] = *(const uint4*)(Bb + q*8);
        }
        __syncthreads();

        #pragma unroll
        for (int ks = 0; ks < 4; ks++) {
            int kk = ks*16 + (lane & 3)*2;
            uint32_t b_[4][2];
            #pragma unroll
            for (int nt = 0; nt < 4; nt++) {
                int col = wc + nt*8 + (lane >> 2);
                b_[nt][0] = *(const uint32_t*)&sm[SM_B + col*APAD + kk];
                b_[nt][1] = *(const uint32_t*)&sm[SM_B + col*APAD + kk + 8];
            }
            #pragma unroll
            for (int mt = 0; mt < 4; mt++) {
                int ra = wr + mt*16 + (lane >> 2);
                uint32_t a0 = *(const uint32_t*)&sm[SM_A + ra*APAD + kk];
                uint32_t a1 = *(const uint32_t*)&sm[SM_A + (ra+8)*APAD + kk];
                uint32_t a2 = *(const uint32_t*)&sm[SM_A + ra*APAD + kk + 8];
                uint32_t a3 = *(const uint32_t*)&sm[SM_A + (ra+8)*APAD + kk + 8];
                #pragma unroll
                for (int nt = 0; nt < 4; nt++)
                    mma_f16(acc[mt*4 + nt], a0, a1, a2, a3, b_[nt][0], b_[nt][1]);
            }
        }
    }

    #pragma unroll
    for (int nt = 0; nt < 4; nt++) {
        int col = wc + nt*8 + (lane & 3)*2;
        float2 bv = *(const float2*)&bi[col];
        #pragma unroll
        for (int mt = 0; mt < 4; mt++) {
            const float* cc = acc[mt*4 + nt];
            int r0 = row0 + wr + mt*16 + (lane >> 2);
            float2 v0, v1;
            v0.x = cc[0] + bv.x; v0.y = cc[1] + bv.y;
            v1.x = cc[2] + bv.x; v1.y = cc[3] + bv.y;
            if (RELU) {
                v0.x = fmaxf(v0.x, 0.f); v0.y = fmaxf(v0.y, 0.f);
                v1.x = fmaxf(v1.x, 0.f); v1.y = fmaxf(v1.y, 0.f);
            }
            if (r0 < NNODES) {
                if (S32) *(float2*)&ho[(size_t)r0*HID + col] = v0;
                if (W16) *(__half2*)&ho16[(size_t)r0*HID + col] = __floats2half2_rn(v0.x, v0.y);
            }
            if (r0 + 8 < NNODES) {
                if (S32) *(float2*)&ho[(size_t)(r0+8)*HID + col] = v1;
                if (W16) *(__half2*)&ho16[(size_t)(r0+8)*HID + col] = __floats2half2_rn(v1.x, v1.y);
            }
        }
    }
}

/* ------------------------------ combine ------------------------------ */
__global__ void k_combine(float* __restrict__ out) {
    int i = blockIdx.x*blockDim.x + threadIdx.x;
    if (i >= NNODES*32) return;
    int n = i >> 5;
    float4 p = *(const float4*)&g_probs[n*NEXP];
    const float4* h4 = (const float4*)g_hA;
    float4 v0 = h4[i];
    float4 v1 = h4[i + (size_t)1*(NNODES*32)];
    float4 v2 = h4[i + (size_t)2*(NNODES*32)];
    float4 v3 = h4[i + (size_t)3*(NNODES*32)];
    float4 r;
    r.x = p.x*v0.x + p.y*v1.x + p.z*v2.x + p.w*v3.x;
    r.y = p.x*v0.y + p.y*v1.y + p.z*v2.y + p.w*v3.y;
    r.z = p.x*v0.z + p.y*v1.z + p.z*v2.z + p.w*v3.z;
    r.w = p.x*v0.w + p.y*v1.w + p.z*v2.w + p.w*v3.w;
    ((float4*)out)[i] = r;
}

/* ------------------------------ launch (prep fork; probs on side stream) ------------------------------ */
extern "C" void kernel_launch(void* const* d_in, const int* in_sizes, int n_in,
                              void* d_out, int out_size) {
    const float* x       = (const float*)d_in[0];
    const void*  ei      = d_in[1];
    const void*  batch   = d_in[2];
    const float* W_enc   = (const float*)d_in[3];
    const float* b_enc   = (const float*)d_in[4];
    const float* W_self  = (const float*)d_in[5];
    const float* W_nbr   = (const float*)d_in[6];
    const float* b_conv  = (const float*)d_in[7];
    const float* centers = (const float*)d_in[8];
    float*       out     = (float*)d_out;

    static cudaStream_t s2 = nullptr;
    static cudaEvent_t  ev0, ev1, evh;
    if (!s2) {
        cudaStreamCreateWithFlags(&s2, cudaStreamNonBlocking);
        cudaEventCreateWithFlags(&ev0, cudaEventDisableTiming);
        cudaEventCreateWithFlags(&ev1, cudaEventDisableTiming);
        cudaEventCreateWithFlags(&evh, cudaEventDisableTiming);
    }

    /* fork: weights + encoder on s2, concurrent with CSR chain on capture stream */
    k_zero_detect<<<NZB, 256>>>((const unsigned int*)ei);
    cudaEventRecord(ev0, 0);
    cudaStreamWaitEvent(s2, ev0, 0);
    k_wsplit_enc<<<NEXP*NLAY + ENCB, 256, 0, s2>>>(W_self, W_nbr, x, W_enc, b_enc);

    k_hist   <<<HEB + 64, 256>>>(ei, batch);
    cudaEventRecord(evh, 0);
    cudaStreamWaitEvent(s2, evh, 0);          /* probs needs g_gcount */
    k_probs  <<<PRBB, 256, 0, s2>>>(batch, centers);
    cudaEventRecord(ev1, s2);

    k_scan1  <<<NB1K, 1024>>>();
    k_scan2  <<<1, 64>>>();
    k_scan3  <<<NB1K, 1024>>>();
    k_scatter<<<HEB, 256>>>(ei);
    cudaStreamWaitEvent(0, ev1, 0);   /* join: encoder h16a + weights + probs ready */

    dim3 gemm_grid(GTILES, NEXP);
    int  spmm_blocks = (NNODES*32 + 255)/256;

    /* layer 0: h0 in bufA slot 0 -> 1 gather; GEMM reads bufA, writes bufB */
    k_spmm16<1><<<spmm_blocks, 256>>>(0);
    k_gemm_mma<true,true,false><<<gemm_grid, 256, SMEM_TOT>>>(0, 0, 1, 0, b_conv);

    /* layer 1: gather bufB -> agg; GEMM bufB -> bufA */
    k_spmm16<4><<<spmm_blocks, 256>>>(1);
    k_gemm_mma<true,true,false><<<gemm_grid, 256, SMEM_TOT>>>(1, (size_t)ESTR, 0, 1, b_conv);

    /* layer 2: gather bufA -> agg; GEMM bufA -> fp32 hA (no relu) */
    k_spmm16<4><<<spmm_blocks, 256>>>(0);
    k_gemm_mma<false,false,true><<<gemm_grid, 256, SMEM_TOT>>>(0, (size_t)ESTR, 0, 2, b_conv);

    /* prior-weighted mix */
    k_combine<<<(NNODES*32 + 255)/256, 256>>>(out);
}